// round 14
// baseline (speedup 1.0000x reference)
#include <cuda_runtime.h>
#include <cuda_fp8.h>
#include <cuda_bf16.h>
#include <cstdint>

// ============================ problem dims ============================
#define MSZ 16384
#define NSZ 2048
#define KSZ 2048

// ============================ GEMM config =============================
#define BM 128
#define BN 256
#define BK 64                     // 64 bf16 = 128 bytes per row per tile
#define KT (KSZ / BK)             // 32 k-tiles
#define STAGES 3
#define ASTRIDE 144               // 128 data + 16 pad: conflict-free LDSM & STS
#define A_SMEM_BYTES (BM * ASTRIDE)   // 18432
#define B_SMEM_BYTES (BN * ASTRIDE)   // 36864
#define STAGE_BYTES (A_SMEM_BYTES + B_SMEM_BYTES)   // 55296
#define SMEM_TOTAL (STAGES * STAGE_BYTES)           // 165888 (1 CTA/SM)

// ============================ scratch =================================
// quantized-to-e4m3 values stored as bf16 (exact: e4m3 has <=4 sig bits)
__device__ __align__(1024) __nv_bfloat16 g_xb[(size_t)MSZ * KSZ];
__device__ __align__(1024) __nv_bfloat16 g_wb[(size_t)NSZ * KSZ];
__device__ float g_amax[2];   // zero at load; atomicMax idempotent across replays

// ============================ PTX helpers =============================
__device__ __forceinline__ uint32_t smem_u32(const void* p) {
    uint32_t a;
    asm("{ .reg .u64 t; cvta.to.shared.u64 t, %1; cvt.u32.u64 %0, t; }"
        : "=r"(a) : "l"(p));
    return a;
}

__device__ __forceinline__ void cp_async16(uint32_t dst, const void* src) {
    asm volatile("cp.async.cg.shared.global [%0], [%1], 16;"
                 :: "r"(dst), "l"(src) : "memory");
}
#define CP_COMMIT() asm volatile("cp.async.commit_group;" ::: "memory")
#define CP_WAIT(n)  asm volatile("cp.async.wait_group %0;" :: "n"(n) : "memory")

__device__ __forceinline__ void ldsm_x4(uint32_t r[4], uint32_t addr) {
    asm volatile("ldmatrix.sync.aligned.m8n8.x4.shared.b16 {%0,%1,%2,%3}, [%4];"
                 : "=r"(r[0]), "=r"(r[1]), "=r"(r[2]), "=r"(r[3])
                 : "r"(addr));
}

__device__ __forceinline__ void mma_bf16(float d[4], const uint32_t a[4],
                                         const uint32_t b[2]) {
    asm volatile(
        "mma.sync.aligned.m16n8k16.row.col.f32.bf16.bf16.f32 "
        "{%0,%1,%2,%3}, {%4,%5,%6,%7}, {%8,%9}, {%0,%1,%2,%3};"
        : "+f"(d[0]), "+f"(d[1]), "+f"(d[2]), "+f"(d[3])
        : "r"(a[0]), "r"(a[1]), "r"(a[2]), "r"(a[3]),
          "r"(b[0]), "r"(b[1]));
}

// f32 -> (scaled, saturate-cast e4m3) -> exact bf16 of that e4m3 value
__device__ __forceinline__ __nv_bfloat162 q2bf(float2 v) {
    __nv_fp8x2_storage_t q = __nv_cvt_float2_to_fp8x2(v, __NV_SATFINITE, __NV_E4M3);
    __half2_raw h2 = __nv_cvt_fp8x2_to_halfraw2(q, __NV_E4M3);
    float2 f = __half22float2(*(__half2*)&h2);
    return __float22bfloat162_rn(f);
}

// ============================ quant kernels ===========================

// x [M,K] f32 -> g_xb [M,K] bf16(e4m3 values, scaled by scale[0]); amax -> g_amax[0]
__global__ void quant_x_kernel(const float* __restrict__ x,
                               const float* __restrict__ scale) {
    const float s = __ldg(&scale[0]);
    const int n4 = (MSZ * KSZ) / 4;
    const int stride = gridDim.x * blockDim.x;
    const float4* x4 = (const float4*)x;
    uint2* q4 = (uint2*)g_xb;
    float amax = 0.0f;
    for (int i = blockIdx.x * blockDim.x + threadIdx.x; i < n4; i += stride) {
        float4 v = x4[i];
        amax = fmaxf(amax, fmaxf(fmaxf(fabsf(v.x), fabsf(v.y)),
                                 fmaxf(fabsf(v.z), fabsf(v.w))));
        __nv_bfloat162 lo = q2bf(make_float2(v.x * s, v.y * s));
        __nv_bfloat162 hi = q2bf(make_float2(v.z * s, v.w * s));
        uint2 o;
        o.x = *(uint32_t*)&lo;
        o.y = *(uint32_t*)&hi;
        q4[i] = o;
    }
    #pragma unroll
    for (int o = 16; o; o >>= 1)
        amax = fmaxf(amax, __shfl_xor_sync(0xFFFFFFFFu, amax, o));
    __shared__ float wmax[8];
    if ((threadIdx.x & 31) == 0) wmax[threadIdx.x >> 5] = amax;
    __syncthreads();
    if (threadIdx.x == 0) {
        float m = wmax[0];
        #pragma unroll
        for (int i = 1; i < 8; i++) m = fmaxf(m, wmax[i]);
        atomicMax((int*)&g_amax[0], __float_as_int(m));
    }
}

// kernel [K,N] f32 -> g_wb [N,K] bf16(e4m3 values, transposed); amax -> g_amax[1]
__global__ void quant_w_kernel(const float* __restrict__ w,
                               const float* __restrict__ scale) {
    __shared__ float tile[32][33];
    const float s = __ldg(&scale[1]);
    const int k0 = blockIdx.y * 32, n0 = blockIdx.x * 32;
    const int tx = threadIdx.x, ty = threadIdx.y;   // block (8, 32)
    const int t = ty * 8 + tx;                      // 0..255
    float amax = 0.0f;
    #pragma unroll
    for (int it = 0; it < 4; it++) {
        int e = it * 256 + t;
        int kk = e >> 5, nn = e & 31;
        float v = w[(size_t)(k0 + kk) * NSZ + n0 + nn];
        amax = fmaxf(amax, fabsf(v));
        tile[kk][nn] = v;
    }
    __syncthreads();
    __nv_bfloat162 p0 = q2bf(make_float2(tile[tx * 4 + 0][ty] * s,
                                         tile[tx * 4 + 1][ty] * s));
    __nv_bfloat162 p1 = q2bf(make_float2(tile[tx * 4 + 2][ty] * s,
                                         tile[tx * 4 + 3][ty] * s));
    uint2 o;
    o.x = *(uint32_t*)&p0;
    o.y = *(uint32_t*)&p1;
    *(uint2*)&g_wb[(size_t)(n0 + ty) * KSZ + k0 + tx * 4] = o;

    #pragma unroll
    for (int of = 16; of; of >>= 1)
        amax = fmaxf(amax, __shfl_xor_sync(0xFFFFFFFFu, amax, of));
    __shared__ float wmax[8];
    if ((t & 31) == 0) wmax[t >> 5] = amax;
    __syncthreads();
    if (t == 0) {
        float m = wmax[0];
        #pragma unroll
        for (int i = 1; i < 8; i++) m = fmaxf(m, wmax[i]);
        atomicMax((int*)&g_amax[1], __float_as_int(m));
    }
}

// faithful _sf_compute + rolled history (all zeros for H=1)
__global__ void scale_update_kernel(const float* __restrict__ scale,
                                    float* __restrict__ tail) {
    int i = threadIdx.x;
    if (i < 2) {
        float a = g_amax[i];
        float s = __ldg(&scale[i]);
        float e = floorf(log2f(448.0f / a));
        float sf = rintf(exp2f(fabsf(e)));
        sf = (a > 0.0f) ? sf : s;
        sf = isinf(a) ? sf : s;
        sf = (e < 0.0f) ? (1.0f / sf) : sf;
        tail[i] = sf;          // new_scale
        tail[2 + i] = 0.0f;    // rolled amax_history
    }
}

// =========================== bf16 GEMM (mma.sync.m16n8k16) ===========
// C[m0:+128, n0:+256] = A @ B^T, A = g_xb [M,K], B = g_wb [N,K] (bf16).
// 512 threads = 16 warps in a 2x8 grid; warp tile 64x32. 1 CTA/SM.
// 3-stage cp.async ring (2 long k-tiles of prefetch depth).
__global__ void __launch_bounds__(512, 1) gemm_kernel(
    float* __restrict__ out, const float* __restrict__ scale)
{
    extern __shared__ char smem[];
    const uint32_t sb = smem_u32(smem);
    const int tid = threadIdx.x, wid = tid >> 5, lane = tid & 31;
    const int m0 = blockIdx.y * BM, n0 = blockIdx.x * BN;
    const int wm = (wid >> 3) * 64, wn = (wid & 7) * 32;

    // ldmatrix lane->row/16B-chunk mapping (identical byte math to the
    // validated fp8 version: one m8n8 b16 matrix row = 16 bytes)
    const int a_row  = ((lane >> 3) & 1) * 8 + (lane & 7);
    const int a_kadd = (lane >> 4) * 16;
    const int b_row  = (lane & 7) + ((lane >> 4) & 1) * 8;
    const int b_kadd = ((lane >> 3) & 1) * 16;

    const uint32_t a_base = sb + (wm + a_row) * ASTRIDE + a_kadd;
    const uint32_t b_base = sb + A_SMEM_BYTES + (wn + b_row) * ASTRIDE + b_kadd;

    // cp.async: row = tid&127 (32 consecutive rows per warp -> 9r mod 32
    // distinct -> conflict-free), k-window = (tid>>7)*32B, 2x16B each.
    const int ldrow = tid & 127;
    const int ldchk = (tid >> 7) * 32;               // 0/32/64/96 bytes
    const uint8_t* ag  = (const uint8_t*)g_xb + (size_t)(m0 + ldrow) * (KSZ * 2) + ldchk;
    const uint8_t* bg0 = (const uint8_t*)g_wb + (size_t)(n0 + ldrow) * (KSZ * 2) + ldchk;
    const uint8_t* bg1 = bg0 + (size_t)128 * (KSZ * 2);
    const uint32_t adst  = sb + ldrow * ASTRIDE + ldchk;
    const uint32_t bdst0 = sb + A_SMEM_BYTES + ldrow * ASTRIDE + ldchk;
    const uint32_t bdst1 = bdst0 + 128 * ASTRIDE;

    float acc[4][4][4] = {};

    // ---- prologue: fill 2 of 3 stages ----
    #pragma unroll
    for (int s = 0; s < STAGES - 1; s++) {
        const uint32_t so = s * STAGE_BYTES;
        const int kb = s * (BK * 2);                 // byte offset per k-tile
        cp_async16(adst + so,       ag + kb);
        cp_async16(adst + so + 16,  ag + kb + 16);
        cp_async16(bdst0 + so,      bg0 + kb);
        cp_async16(bdst0 + so + 16, bg0 + kb + 16);
        cp_async16(bdst1 + so,      bg1 + kb);
        cp_async16(bdst1 + so + 16, bg1 + kb + 16);
        CP_COMMIT();
    }

    uint32_t so = 0;                                 // compute-stage offset
    uint32_t no = (STAGES - 1) * STAGE_BYTES;        // next-load-stage offset
    for (int it = 0; it < KT; it++) {
        CP_WAIT(STAGES - 2);
        __syncthreads();

        const int nxt = it + STAGES - 1;
        if (nxt < KT) {
            const int kb = nxt * (BK * 2);
            cp_async16(adst + no,       ag + kb);
            cp_async16(adst + no + 16,  ag + kb + 16);
            cp_async16(bdst0 + no,      bg0 + kb);
            cp_async16(bdst0 + no + 16, bg0 + kb + 16);
            cp_async16(bdst1 + no,      bg1 + kb);
            cp_async16(bdst1 + no + 16, bg1 + kb + 16);
        }
        CP_COMMIT();
        no += STAGE_BYTES; if (no == SMEM_TOTAL) no = 0;

        // ---- 4 ksteps of k16: 6 LDSM + 16 HMMA each ----
        #pragma unroll
        for (int ks = 0; ks < 4; ks++) {
            const uint32_t kb = so + ks * 32;        // 16 bf16 = 32 bytes
            uint32_t afr[4][4], bfr[4][2];
            #pragma unroll
            for (int mt = 0; mt < 4; mt++)
                ldsm_x4(afr[mt], a_base + kb + mt * (16 * ASTRIDE));
            #pragma unroll
            for (int np = 0; np < 2; np++) {
                uint32_t r[4];
                ldsm_x4(r, b_base + kb + np * (16 * ASTRIDE));
                bfr[2 * np][0]     = r[0];
                bfr[2 * np][1]     = r[1];
                bfr[2 * np + 1][0] = r[2];
                bfr[2 * np + 1][1] = r[3];
            }
            #pragma unroll
            for (int mt = 0; mt < 4; mt++)
                #pragma unroll
                for (int nt = 0; nt < 4; nt++)
                    mma_bf16(acc[mt][nt], afr[mt], bfr[nt]);
        }

        so += STAGE_BYTES; if (so == SMEM_TOTAL) so = 0;
    }

    // ---- epilogue ----
    const float inv = (1.0f / __ldg(&scale[0])) * (1.0f / __ldg(&scale[1]));
    const int lrow = lane >> 2;
    #pragma unroll
    for (int mt = 0; mt < 4; mt++) {
        const int row = m0 + wm + mt * 16 + lrow;
        #pragma unroll
        for (int nt = 0; nt < 4; nt++) {
            const int col = n0 + wn + nt * 8 + (lane & 3) * 2;
            float2 v0 = make_float2(acc[mt][nt][0] * inv, acc[mt][nt][1] * inv);
            float2 v1 = make_float2(acc[mt][nt][2] * inv, acc[mt][nt][3] * inv);
            *(float2*)&out[(size_t)row * NSZ + col] = v0;
            *(float2*)&out[(size_t)(row + 8) * NSZ + col] = v1;
        }
    }
}

// ============================ host launch =============================
extern "C" void kernel_launch(void* const* d_in, const int* in_sizes, int n_in,
                              void* d_out, int out_size) {
    const float* x     = (const float*)d_in[0];
    const float* w     = (const float*)d_in[1];
    const float* scale = (const float*)d_in[2];
    float* out = (float*)d_out;

    // launch order keeps the GEMM at sampled index 3 for ncu
    quant_x_kernel<<<1184, 256>>>(x, scale);                                   // 0
    quant_w_kernel<<<dim3(NSZ / 32, KSZ / 32), dim3(8, 32)>>>(w, scale);       // 1
    scale_update_kernel<<<1, 32>>>(scale, out + (out_size - 4));               // 2

    static bool attr_set = false;
    if (!attr_set) {
        cudaFuncSetAttribute(gemm_kernel,
                             cudaFuncAttributeMaxDynamicSharedMemorySize,
                             SMEM_TOTAL);
        attr_set = true;
    }
    gemm_kernel<<<dim3(NSZ / BN, MSZ / BM), 512, SMEM_TOTAL>>>(out, scale);    // 3
}

// round 15
// speedup vs baseline: 1.3570x; 1.3570x over previous
#include <cuda_runtime.h>
#include <cuda_fp8.h>
#include <cuda_fp16.h>
#include <cstdint>

// ============================ problem dims ============================
#define MSZ 16384
#define NSZ 2048
#define KSZ 2048

// ============================ GEMM config =============================
#define BM 128
#define BN 256
#define BK 64                 // 64 fp8 bytes per row per k-tile (4 k16 groups)
#define KT (KSZ / BK)         // 32 k-tiles
#define STAGES 6
#define ASTRIDE 80            // 64 data + 16 pad: conflict-free LDSM & STS
#define A_SMEM_BYTES (BM * ASTRIDE)   // 10240
#define B_SMEM_BYTES (BN * ASTRIDE)   // 20480
#define STAGE_BYTES (A_SMEM_BYTES + B_SMEM_BYTES)   // 30720
#define SMEM_TOTAL (STAGES * STAGE_BYTES)           // 184320 (1 CTA/SM)

// ============================ scratch =================================
// e4m3 bytes, k16-group pair-interleaved: [k0k1 k8k9 k2k3 k10k11 ...]
__device__ __align__(1024) uint8_t g_xq[(size_t)MSZ * KSZ];
__device__ __align__(1024) uint8_t g_wq[(size_t)NSZ * KSZ];
__device__ float g_amax[2];   // zero at load; atomicMax idempotent across replays

// ============================ PTX helpers =============================
__device__ __forceinline__ uint32_t smem_u32(const void* p) {
    uint32_t a;
    asm("{ .reg .u64 t; cvta.to.shared.u64 t, %1; cvt.u32.u64 %0, t; }"
        : "=r"(a) : "l"(p));
    return a;
}

__device__ __forceinline__ void cp_async16(uint32_t dst, const void* src) {
    asm volatile("cp.async.cg.shared.global [%0], [%1], 16;"
                 :: "r"(dst), "l"(src) : "memory");
}
#define CP_COMMIT() asm volatile("cp.async.commit_group;" ::: "memory")
#define CP_WAIT(n)  asm volatile("cp.async.wait_group %0;" :: "n"(n) : "memory")

__device__ __forceinline__ void ldsm_x4(uint32_t r[4], uint32_t addr) {
    asm volatile("ldmatrix.sync.aligned.m8n8.x4.shared.b16 {%0,%1,%2,%3}, [%4];"
                 : "=r"(r[0]), "=r"(r[1]), "=r"(r[2]), "=r"(r[3])
                 : "r"(addr));
}

// packed e4m3x2 (16 bits) -> f16x2 (32 bits), exact
__device__ __forceinline__ uint32_t cvt2(uint32_t x) {
    __half2_raw h = __nv_cvt_fp8x2_to_halfraw2((__nv_fp8x2_storage_t)x, __NV_E4M3);
    return *(uint32_t*)&h;
}

__device__ __forceinline__ void mma_f16(float d[4], const uint32_t a[4],
                                        const uint32_t b[2]) {
    asm volatile(
        "mma.sync.aligned.m16n8k16.row.col.f32.f16.f16.f32 "
        "{%0,%1,%2,%3}, {%4,%5,%6,%7}, {%8,%9}, {%0,%1,%2,%3};"
        : "+f"(d[0]), "+f"(d[1]), "+f"(d[2]), "+f"(d[3])
        : "r"(a[0]), "r"(a[1]), "r"(a[2]), "r"(a[3]),
          "r"(b[0]), "r"(b[1]));
}

// quantize float2 -> packed e4m3x2 (uint16)
__device__ __forceinline__ uint32_t qpair(float a, float b) {
    return (uint32_t)__nv_cvt_float2_to_fp8x2(make_float2(a, b),
                                              __NV_SATFINITE, __NV_E4M3);
}

// ============================ quant kernels ===========================

// x [M,K] f32 -> g_xq [M,K] e4m3 (scaled, k16-interleaved); amax -> g_amax[0]
// each thread handles one 16-element k-group per iteration.
__global__ void quant_x_kernel(const float* __restrict__ x,
                               const float* __restrict__ scale) {
    const float s = __ldg(&scale[0]);
    const int ngrp = (MSZ * KSZ) / 16;
    const int stride = gridDim.x * blockDim.x;
    float amax = 0.0f;
    for (int g = blockIdx.x * blockDim.x + threadIdx.x; g < ngrp; g += stride) {
        const float4* xg = (const float4*)(x + (size_t)g * 16);
        float4 v0 = xg[0], v1 = xg[1], v2 = xg[2], v3 = xg[3];
        amax = fmaxf(amax, fmaxf(
            fmaxf(fmaxf(fabsf(v0.x), fabsf(v0.y)), fmaxf(fabsf(v0.z), fabsf(v0.w))),
            fmaxf(fmaxf(fabsf(v1.x), fabsf(v1.y)), fmaxf(fabsf(v1.z), fabsf(v1.w)))));
        amax = fmaxf(amax, fmaxf(
            fmaxf(fmaxf(fabsf(v2.x), fabsf(v2.y)), fmaxf(fabsf(v2.z), fabsf(v2.w))),
            fmaxf(fmaxf(fabsf(v3.x), fabsf(v3.y)), fmaxf(fabsf(v3.z), fabsf(v3.w)))));
        // logical pairs p0..p7
        uint32_t p0 = qpair(v0.x * s, v0.y * s);
        uint32_t p1 = qpair(v0.z * s, v0.w * s);
        uint32_t p2 = qpair(v1.x * s, v1.y * s);
        uint32_t p3 = qpair(v1.z * s, v1.w * s);
        uint32_t p4 = qpair(v2.x * s, v2.y * s);
        uint32_t p5 = qpair(v2.z * s, v2.w * s);
        uint32_t p6 = qpair(v3.x * s, v3.y * s);
        uint32_t p7 = qpair(v3.z * s, v3.w * s);
        // interleaved storage: [p0 p4][p1 p5][p2 p6][p3 p7]
        uint4 o;
        o.x = p0 | (p4 << 16);
        o.y = p1 | (p5 << 16);
        o.z = p2 | (p6 << 16);
        o.w = p3 | (p7 << 16);
        *(uint4*)(g_xq + (size_t)g * 16) = o;
    }
    #pragma unroll
    for (int o = 16; o; o >>= 1)
        amax = fmaxf(amax, __shfl_xor_sync(0xFFFFFFFFu, amax, o));
    __shared__ float wmax[8];
    if ((threadIdx.x & 31) == 0) wmax[threadIdx.x >> 5] = amax;
    __syncthreads();
    if (threadIdx.x == 0) {
        float m = wmax[0];
        #pragma unroll
        for (int i = 1; i < 8; i++) m = fmaxf(m, wmax[i]);
        atomicMax((int*)&g_amax[0], __float_as_int(m));
    }
}

// kernel [K,N] f32 -> g_wq [N,K] e4m3 (transpose, scaled, k16-interleaved)
__global__ void quant_w_kernel(const float* __restrict__ w,
                               const float* __restrict__ scale) {
    __shared__ float tile[32][33];
    const float s = __ldg(&scale[1]);
    const int k0 = blockIdx.y * 32, n0 = blockIdx.x * 32;
    const int tx = threadIdx.x, ty = threadIdx.y;   // block (8, 32)
    const int t = ty * 8 + tx;                      // 0..255
    float amax = 0.0f;
    #pragma unroll
    for (int it = 0; it < 4; it++) {
        int e = it * 256 + t;
        int kk = e >> 5, nn = e & 31;
        float v = w[(size_t)(k0 + kk) * NSZ + n0 + nn];
        amax = fmaxf(amax, fabsf(v));
        tile[kk][nn] = v;
    }
    __syncthreads();
    // threads 0..63: n = t>>1, k16-group = t&1
    if (t < 64) {
        const int n = t >> 1, kb = (t & 1) * 16;
        uint32_t p[8];
        #pragma unroll
        for (int j = 0; j < 8; j++)
            p[j] = qpair(tile[kb + 2 * j][n] * s, tile[kb + 2 * j + 1][n] * s);
        uint4 o;
        o.x = p[0] | (p[4] << 16);
        o.y = p[1] | (p[5] << 16);
        o.z = p[2] | (p[6] << 16);
        o.w = p[3] | (p[7] << 16);
        *(uint4*)(g_wq + (size_t)(n0 + n) * KSZ + k0 + kb) = o;
    }

    #pragma unroll
    for (int of = 16; of; of >>= 1)
        amax = fmaxf(amax, __shfl_xor_sync(0xFFFFFFFFu, amax, of));
    __shared__ float wmax[8];
    if ((t & 31) == 0) wmax[t >> 5] = amax;
    __syncthreads();
    if (t == 0) {
        float m = wmax[0];
        #pragma unroll
        for (int i = 1; i < 8; i++) m = fmaxf(m, wmax[i]);
        atomicMax((int*)&g_amax[1], __float_as_int(m));
    }
}

// faithful _sf_compute + rolled history (all zeros for H=1)
__global__ void scale_update_kernel(const float* __restrict__ scale,
                                    float* __restrict__ tail) {
    int i = threadIdx.x;
    if (i < 2) {
        float a = g_amax[i];
        float s = __ldg(&scale[i]);
        float e = floorf(log2f(448.0f / a));
        float sf = rintf(exp2f(fabsf(e)));
        sf = (a > 0.0f) ? sf : s;
        sf = isinf(a) ? sf : s;
        sf = (e < 0.0f) ? (1.0f / sf) : sf;
        tail[i] = sf;          // new_scale
        tail[2 + i] = 0.0f;    // rolled amax_history
    }
}

// ================= GEMM: fp8 smem -> cvt once -> fp16 HMMA ===========
// C[m0:+128, n0:+256] = A @ B^T. 512 threads, 16 warps (2x8), warp tile
// 64x32. 6-stage cp.async ring of fp8 tiles; per k16 step: 3 LDSM.x4,
// 24 cvt (once per element), 16 HMMA.16816.f16.
__global__ void __launch_bounds__(512, 1) gemm_kernel(
    float* __restrict__ out, const float* __restrict__ scale)
{
    extern __shared__ char smem[];
    const uint32_t sb = smem_u32(smem);
    const int tid = threadIdx.x, wid = tid >> 5, lane = tid & 31;
    const int m0 = blockIdx.y * BM, n0 = blockIdx.x * BN;
    const int wm = (wid >> 3) * 64, wn = (wid & 7) * 32;

    // LDSM row = lane (matrix = lane>>3 maps rows 8m..8m+7)
    const uint32_t a_base = sb + (wm + lane) * ASTRIDE;
    const uint32_t b_base = sb + A_SMEM_BYTES + (wn + lane) * ASTRIDE;

    // cp.async: row = tid&127, chunk = (tid>>7)*16 (conflict-free, R13-proven)
    const int ldrow = tid & 127;
    const int ldchk = (tid >> 7) * 16;
    const uint8_t* ag  = g_xq + (size_t)(m0 + ldrow) * KSZ + ldchk;
    const uint8_t* bg0 = g_wq + (size_t)(n0 + ldrow) * KSZ + ldchk;
    const uint8_t* bg1 = bg0 + (size_t)128 * KSZ;
    const uint32_t adst  = sb + ldrow * ASTRIDE + ldchk;
    const uint32_t bdst0 = sb + A_SMEM_BYTES + ldrow * ASTRIDE + ldchk;
    const uint32_t bdst1 = bdst0 + 128 * ASTRIDE;

    float acc[4][4][4] = {};

    // ---- prologue: fill 5 of 6 stages ----
    #pragma unroll
    for (int s = 0; s < STAGES - 1; s++) {
        const uint32_t so = s * STAGE_BYTES;
        const int k0 = s * BK;
        cp_async16(adst + so,  ag + k0);
        cp_async16(bdst0 + so, bg0 + k0);
        cp_async16(bdst1 + so, bg1 + k0);
        CP_COMMIT();
    }

    uint32_t so = 0;
    uint32_t no = (STAGES - 1) * STAGE_BYTES;
    for (int it = 0; it < KT; it++) {
        CP_WAIT(STAGES - 2);
        __syncthreads();

        const int nxt = it + STAGES - 1;
        if (nxt < KT) {
            const int k0 = nxt * BK;
            cp_async16(adst + no,  ag + k0);
            cp_async16(bdst0 + no, bg0 + k0);
            cp_async16(bdst1 + no, bg1 + k0);
        }
        CP_COMMIT();
        no += STAGE_BYTES; if (no == SMEM_TOTAL) no = 0;

        // ---- 4 ksteps of k16 (16 fp8 bytes) ----
        #pragma unroll
        for (int ks = 0; ks < 4; ks++) {
            const uint32_t kb = so + ks * 16;
            uint32_t ar0[4], ar1[4], br[4];
            ldsm_x4(ar0, a_base + kb);                    // rows wm+0..31
            ldsm_x4(ar1, a_base + kb + 32 * ASTRIDE);     // rows wm+32..63
            ldsm_x4(br,  b_base + kb);                    // n-rows wn+0..31

            // convert once per element: fp8x4 (b32) -> 2x f16x2
            uint32_t A[4][4], B[4][2];
            #pragma unroll
            for (int sub = 0; sub < 2; sub++) {
                // m-tiles 0,1 from ar0; 2,3 from ar1
                A[sub][0]     = cvt2(ar0[2 * sub] & 0xFFFFu);
                A[sub][2]     = cvt2(ar0[2 * sub] >> 16);
                A[sub][1]     = cvt2(ar0[2 * sub + 1] & 0xFFFFu);
                A[sub][3]     = cvt2(ar0[2 * sub + 1] >> 16);
                A[sub + 2][0] = cvt2(ar1[2 * sub] & 0xFFFFu);
                A[sub + 2][2] = cvt2(ar1[2 * sub] >> 16);
                A[sub + 2][1] = cvt2(ar1[2 * sub + 1] & 0xFFFFu);
                A[sub + 2][3] = cvt2(ar1[2 * sub + 1] >> 16);
            }
            #pragma unroll
            for (int nt = 0; nt < 4; nt++) {
                B[nt][0] = cvt2(br[nt] & 0xFFFFu);
                B[nt][1] = cvt2(br[nt] >> 16);
            }
            #pragma unroll
            for (int mt = 0; mt < 4; mt++)
                #pragma unroll
                for (int nt = 0; nt < 4; nt++)
                    mma_f16(acc[mt][nt], A[mt], B[nt]);
        }

        so += STAGE_BYTES; if (so == SMEM_TOTAL) so = 0;
    }

    // ---- epilogue ----
    const float inv = (1.0f / __ldg(&scale[0])) * (1.0f / __ldg(&scale[1]));
    const int lrow = lane >> 2;
    #pragma unroll
    for (int mt = 0; mt < 4; mt++) {
        const int row = m0 + wm + mt * 16 + lrow;
        #pragma unroll
        for (int nt = 0; nt < 4; nt++) {
            const int col = n0 + wn + nt * 8 + (lane & 3) * 2;
            float2 v0 = make_float2(acc[mt][nt][0] * inv, acc[mt][nt][1] * inv);
            float2 v1 = make_float2(acc[mt][nt][2] * inv, acc[mt][nt][3] * inv);
            *(float2*)&out[(size_t)row * NSZ + col] = v0;
            *(float2*)&out[(size_t)(row + 8) * NSZ + col] = v1;
        }
    }
}

// ============================ host launch =============================
extern "C" void kernel_launch(void* const* d_in, const int* in_sizes, int n_in,
                              void* d_out, int out_size) {
    const float* x     = (const float*)d_in[0];
    const float* w     = (const float*)d_in[1];
    const float* scale = (const float*)d_in[2];
    float* out = (float*)d_out;

    // launch order keeps the GEMM at sampled index 3 for ncu
    quant_x_kernel<<<1184, 256>>>(x, scale);                                   // 0
    quant_w_kernel<<<dim3(NSZ / 32, KSZ / 32), dim3(8, 32)>>>(w, scale);       // 1
    scale_update_kernel<<<1, 32>>>(scale, out + (out_size - 4));               // 2

    static bool attr_set = false;
    if (!attr_set) {
        cudaFuncSetAttribute(gemm_kernel,
                             cudaFuncAttributeMaxDynamicSharedMemorySize,
                             SMEM_TOTAL);
        attr_set = true;
    }
    gemm_kernel<<<dim3(NSZ / BN, MSZ / BM), 512, SMEM_TOTAL>>>(out, scale);    // 3
}

// round 16
// speedup vs baseline: 1.6122x; 1.1881x over previous
#include <cuda_runtime.h>
#include <cuda_fp8.h>
#include <cuda_fp16.h>
#include <cstdint>

// ============================ problem dims ============================
#define MSZ 16384
#define NSZ 2048
#define KSZ 2048

// ============================ GEMM config =============================
#define BM 128
#define BN 256
#define BK 128                // 128 fp8 bytes per row per k-tile (8 k16 groups)
#define KT (KSZ / BK)         // 16 k-tiles
#define STAGES 3
#define ASTRIDE 144           // 128 data + 16 pad: conflict-free LDSM & STS
#define A_SMEM_BYTES (BM * ASTRIDE)   // 18432
#define B_SMEM_BYTES (BN * ASTRIDE)   // 36864
#define STAGE_BYTES (A_SMEM_BYTES + B_SMEM_BYTES)   // 55296
#define SMEM_TOTAL (STAGES * STAGE_BYTES)           // 165888 (1 CTA/SM)

// ============================ scratch =================================
// e4m3 bytes, k16-group pair-interleaved: [k0k1 k8k9 k2k3 k10k11 ...]
__device__ __align__(1024) uint8_t g_xq[(size_t)MSZ * KSZ];
__device__ __align__(1024) uint8_t g_wq[(size_t)NSZ * KSZ];
__device__ float g_amax[2];   // zero at load; atomicMax idempotent across replays

// ============================ PTX helpers =============================
__device__ __forceinline__ uint32_t smem_u32(const void* p) {
    uint32_t a;
    asm("{ .reg .u64 t; cvta.to.shared.u64 t, %1; cvt.u32.u64 %0, t; }"
        : "=r"(a) : "l"(p));
    return a;
}

__device__ __forceinline__ void cp_async16(uint32_t dst, const void* src) {
    asm volatile("cp.async.cg.shared.global [%0], [%1], 16;"
                 :: "r"(dst), "l"(src) : "memory");
}
#define CP_COMMIT() asm volatile("cp.async.commit_group;" ::: "memory")
#define CP_WAIT(n)  asm volatile("cp.async.wait_group %0;" :: "n"(n) : "memory")

__device__ __forceinline__ void ldsm_x4(uint32_t* r, uint32_t addr) {
    asm volatile("ldmatrix.sync.aligned.m8n8.x4.shared.b16 {%0,%1,%2,%3}, [%4];"
                 : "=r"(r[0]), "=r"(r[1]), "=r"(r[2]), "=r"(r[3])
                 : "r"(addr));
}

// packed e4m3x2 (low 16 bits) -> f16x2, exact
__device__ __forceinline__ uint32_t cvt2(uint32_t x) {
    __half2_raw h = __nv_cvt_fp8x2_to_halfraw2((__nv_fp8x2_storage_t)x, __NV_E4M3);
    return *(uint32_t*)&h;
}

__device__ __forceinline__ void mma_f16(float d[4], const uint32_t a[4],
                                        const uint32_t b[2]) {
    asm volatile(
        "mma.sync.aligned.m16n8k16.row.col.f32.f16.f16.f32 "
        "{%0,%1,%2,%3}, {%4,%5,%6,%7}, {%8,%9}, {%0,%1,%2,%3};"
        : "+f"(d[0]), "+f"(d[1]), "+f"(d[2]), "+f"(d[3])
        : "r"(a[0]), "r"(a[1]), "r"(a[2]), "r"(a[3]),
          "r"(b[0]), "r"(b[1]));
}

// quantize float2 -> packed e4m3x2 (uint16)
__device__ __forceinline__ uint32_t qpair(float a, float b) {
    return (uint32_t)__nv_cvt_float2_to_fp8x2(make_float2(a, b),
                                              __NV_SATFINITE, __NV_E4M3);
}

// ============================ quant kernels ===========================

// x [M,K] f32 -> g_xq [M,K] e4m3 (scaled, k16-interleaved); amax -> g_amax[0]
__global__ void quant_x_kernel(const float* __restrict__ x,
                               const float* __restrict__ scale) {
    const float s = __ldg(&scale[0]);
    const int ngrp = (MSZ * KSZ) / 16;
    const int stride = gridDim.x * blockDim.x;
    float amax = 0.0f;
    for (int g = blockIdx.x * blockDim.x + threadIdx.x; g < ngrp; g += stride) {
        const float4* xg = (const float4*)(x + (size_t)g * 16);
        float4 v0 = xg[0], v1 = xg[1], v2 = xg[2], v3 = xg[3];
        amax = fmaxf(amax, fmaxf(
            fmaxf(fmaxf(fabsf(v0.x), fabsf(v0.y)), fmaxf(fabsf(v0.z), fabsf(v0.w))),
            fmaxf(fmaxf(fabsf(v1.x), fabsf(v1.y)), fmaxf(fabsf(v1.z), fabsf(v1.w)))));
        amax = fmaxf(amax, fmaxf(
            fmaxf(fmaxf(fabsf(v2.x), fabsf(v2.y)), fmaxf(fabsf(v2.z), fabsf(v2.w))),
            fmaxf(fmaxf(fabsf(v3.x), fabsf(v3.y)), fmaxf(fabsf(v3.z), fabsf(v3.w)))));
        uint32_t p0 = qpair(v0.x * s, v0.y * s);
        uint32_t p1 = qpair(v0.z * s, v0.w * s);
        uint32_t p2 = qpair(v1.x * s, v1.y * s);
        uint32_t p3 = qpair(v1.z * s, v1.w * s);
        uint32_t p4 = qpair(v2.x * s, v2.y * s);
        uint32_t p5 = qpair(v2.z * s, v2.w * s);
        uint32_t p6 = qpair(v3.x * s, v3.y * s);
        uint32_t p7 = qpair(v3.z * s, v3.w * s);
        uint4 o;
        o.x = p0 | (p4 << 16);
        o.y = p1 | (p5 << 16);
        o.z = p2 | (p6 << 16);
        o.w = p3 | (p7 << 16);
        *(uint4*)(g_xq + (size_t)g * 16) = o;
    }
    #pragma unroll
    for (int o = 16; o; o >>= 1)
        amax = fmaxf(amax, __shfl_xor_sync(0xFFFFFFFFu, amax, o));
    __shared__ float wmax[8];
    if ((threadIdx.x & 31) == 0) wmax[threadIdx.x >> 5] = amax;
    __syncthreads();
    if (threadIdx.x == 0) {
        float m = wmax[0];
        #pragma unroll
        for (int i = 1; i < 8; i++) m = fmaxf(m, wmax[i]);
        atomicMax((int*)&g_amax[0], __float_as_int(m));
    }
}

// kernel [K,N] f32 -> g_wq [N,K] e4m3 (transpose, scaled, k16-interleaved)
__global__ void quant_w_kernel(const float* __restrict__ w,
                               const float* __restrict__ scale) {
    __shared__ float tile[32][33];
    const float s = __ldg(&scale[1]);
    const int k0 = blockIdx.y * 32, n0 = blockIdx.x * 32;
    const int tx = threadIdx.x, ty = threadIdx.y;   // block (8, 32)
    const int t = ty * 8 + tx;                      // 0..255
    float amax = 0.0f;
    #pragma unroll
    for (int it = 0; it < 4; it++) {
        int e = it * 256 + t;
        int kk = e >> 5, nn = e & 31;
        float v = w[(size_t)(k0 + kk) * NSZ + n0 + nn];
        amax = fmaxf(amax, fabsf(v));
        tile[kk][nn] = v;
    }
    __syncthreads();
    if (t < 64) {
        const int n = t >> 1, kb = (t & 1) * 16;
        uint32_t p[8];
        #pragma unroll
        for (int j = 0; j < 8; j++)
            p[j] = qpair(tile[kb + 2 * j][n] * s, tile[kb + 2 * j + 1][n] * s);
        uint4 o;
        o.x = p[0] | (p[4] << 16);
        o.y = p[1] | (p[5] << 16);
        o.z = p[2] | (p[6] << 16);
        o.w = p[3] | (p[7] << 16);
        *(uint4*)(g_wq + (size_t)(n0 + n) * KSZ + k0 + kb) = o;
    }

    #pragma unroll
    for (int of = 16; of; of >>= 1)
        amax = fmaxf(amax, __shfl_xor_sync(0xFFFFFFFFu, amax, of));
    __shared__ float wmax[8];
    if ((t & 31) == 0) wmax[t >> 5] = amax;
    __syncthreads();
    if (t == 0) {
        float m = wmax[0];
        #pragma unroll
        for (int i = 1; i < 8; i++) m = fmaxf(m, wmax[i]);
        atomicMax((int*)&g_amax[1], __float_as_int(m));
    }
}

// faithful _sf_compute + rolled history (all zeros for H=1)
__global__ void scale_update_kernel(const float* __restrict__ scale,
                                    float* __restrict__ tail) {
    int i = threadIdx.x;
    if (i < 2) {
        float a = g_amax[i];
        float s = __ldg(&scale[i]);
        float e = floorf(log2f(448.0f / a));
        float sf = rintf(exp2f(fabsf(e)));
        sf = (a > 0.0f) ? sf : s;
        sf = isinf(a) ? sf : s;
        sf = (e < 0.0f) ? (1.0f / sf) : sf;
        tail[i] = sf;          // new_scale
        tail[2 + i] = 0.0f;    // rolled amax_history
    }
}

// ================= GEMM: fp8 smem -> cvt once -> fp16 HMMA ===========
// C[m0:+128, n0:+256] = A @ B^T. 512 threads, 16 warps (2x8), warp tile
// 64x32. BK=128 (8 k16 steps per tile, 16 iters). 3-stage cp.async ring.
// Raw fp8 fragments double-buffered: LDSM for kstep+1 issues before the
// cvt+HMMA of kstep -> LDS latency hidden under tensor work.
__global__ void __launch_bounds__(512, 1) gemm_kernel(
    float* __restrict__ out, const float* __restrict__ scale)
{
    extern __shared__ char smem[];
    const uint32_t sb = smem_u32(smem);
    const int tid = threadIdx.x, wid = tid >> 5, lane = tid & 31;
    const int m0 = blockIdx.y * BM, n0 = blockIdx.x * BN;
    const int wm = (wid >> 3) * 64, wn = (wid & 7) * 32;

    // LDSM row = lane
    const uint32_t a_base = sb + (wm + lane) * ASTRIDE;
    const uint32_t b_base = sb + A_SMEM_BYTES + (wn + lane) * ASTRIDE;

    // cp.async: A row = tid>>2, col (tid&3)*32 (+16); B rows tid>>2 and +128.
    const int ldrow = tid >> 2;            // 0..127
    const int ldcol = (tid & 3) * 32;      // 0/32/64/96
    const uint8_t* ag  = g_xq + (size_t)(m0 + ldrow) * KSZ + ldcol;
    const uint8_t* bg0 = g_wq + (size_t)(n0 + ldrow) * KSZ + ldcol;
    const uint8_t* bg1 = bg0 + (size_t)128 * KSZ;
    const uint32_t adst  = sb + ldrow * ASTRIDE + ldcol;
    const uint32_t bdst0 = sb + A_SMEM_BYTES + ldrow * ASTRIDE + ldcol;
    const uint32_t bdst1 = bdst0 + 128 * ASTRIDE;

    float acc[4][4][4] = {};

    // ---- prologue: fill 2 of 3 stages ----
    #pragma unroll
    for (int s = 0; s < STAGES - 1; s++) {
        const uint32_t so = s * STAGE_BYTES;
        const int k0 = s * BK;
        cp_async16(adst + so,       ag + k0);
        cp_async16(adst + so + 16,  ag + k0 + 16);
        cp_async16(bdst0 + so,      bg0 + k0);
        cp_async16(bdst0 + so + 16, bg0 + k0 + 16);
        cp_async16(bdst1 + so,      bg1 + k0);
        cp_async16(bdst1 + so + 16, bg1 + k0 + 16);
        CP_COMMIT();
    }

    uint32_t so = 0;
    uint32_t no = (STAGES - 1) * STAGE_BYTES;
    for (int it = 0; it < KT; it++) {
        CP_WAIT(STAGES - 2);
        __syncthreads();

        const int nxt = it + STAGES - 1;
        if (nxt < KT) {
            const int k0 = nxt * BK;
            cp_async16(adst + no,       ag + k0);
            cp_async16(adst + no + 16,  ag + k0 + 16);
            cp_async16(bdst0 + no,      bg0 + k0);
            cp_async16(bdst0 + no + 16, bg0 + k0 + 16);
            cp_async16(bdst1 + no,      bg1 + k0);
            cp_async16(bdst1 + no + 16, bg1 + k0 + 16);
        }
        CP_COMMIT();
        no += STAGE_BYTES; if (no == SMEM_TOTAL) no = 0;

        // ---- 8 ksteps, raw fragments double-buffered ----
        // raw[buf][0..3]=A rows wm..wm+31, [4..7]=A rows wm+32..63, [8..11]=B
        uint32_t raw[2][12];
        ldsm_x4(&raw[0][0], a_base + so);
        ldsm_x4(&raw[0][4], a_base + so + 32 * ASTRIDE);
        ldsm_x4(&raw[0][8], b_base + so);
        #pragma unroll
        for (int ks = 0; ks < 8; ks++) {
            const int cur = ks & 1, nxtb = cur ^ 1;
            if (ks < 7) {
                const uint32_t kb = so + (ks + 1) * 16;
                ldsm_x4(&raw[nxtb][0], a_base + kb);
                ldsm_x4(&raw[nxtb][4], a_base + kb + 32 * ASTRIDE);
                ldsm_x4(&raw[nxtb][8], b_base + kb);
            }
            // convert B once (8 cvt), then per mt: 4 cvt + 4 HMMA
            uint32_t B[4][2];
            #pragma unroll
            for (int nt = 0; nt < 4; nt++) {
                B[nt][0] = cvt2(raw[cur][8 + nt] & 0xFFFFu);
                B[nt][1] = cvt2(raw[cur][8 + nt] >> 16);
            }
            #pragma unroll
            for (int mt = 0; mt < 4; mt++) {
                uint32_t A[4];
                A[0] = cvt2(raw[cur][2 * mt] & 0xFFFFu);
                A[2] = cvt2(raw[cur][2 * mt] >> 16);
                A[1] = cvt2(raw[cur][2 * mt + 1] & 0xFFFFu);
                A[3] = cvt2(raw[cur][2 * mt + 1] >> 16);
                #pragma unroll
                for (int nt = 0; nt < 4; nt++)
                    mma_f16(acc[mt][nt], A, B[nt]);
            }
        }

        so += STAGE_BYTES; if (so == SMEM_TOTAL) so = 0;
    }

    // ---- epilogue ----
    const float inv = (1.0f / __ldg(&scale[0])) * (1.0f / __ldg(&scale[1]));
    const int lrow = lane >> 2;
    #pragma unroll
    for (int mt = 0; mt < 4; mt++) {
        const int row = m0 + wm + mt * 16 + lrow;
        #pragma unroll
        for (int nt = 0; nt < 4; nt++) {
            const int col = n0 + wn + nt * 8 + (lane & 3) * 2;
            float2 v0 = make_float2(acc[mt][nt][0] * inv, acc[mt][nt][1] * inv);
            float2 v1 = make_float2(acc[mt][nt][2] * inv, acc[mt][nt][3] * inv);
            *(float2*)&out[(size_t)row * NSZ + col] = v0;
            *(float2*)&out[(size_t)(row + 8) * NSZ + col] = v1;
        }
    }
}

// ============================ host launch =============================
extern "C" void kernel_launch(void* const* d_in, const int* in_sizes, int n_in,
                              void* d_out, int out_size) {
    const float* x     = (const float*)d_in[0];
    const float* w     = (const float*)d_in[1];
    const float* scale = (const float*)d_in[2];
    float* out = (float*)d_out;

    // launch order keeps the GEMM at sampled index 3 for ncu
    quant_x_kernel<<<1184, 256>>>(x, scale);                                   // 0
    quant_w_kernel<<<dim3(NSZ / 32, KSZ / 32), dim3(8, 32)>>>(w, scale);       // 1
    scale_update_kernel<<<1, 32>>>(scale, out + (out_size - 4));               // 2

    static bool attr_set = false;
    if (!attr_set) {
        cudaFuncSetAttribute(gemm_kernel,
                             cudaFuncAttributeMaxDynamicSharedMemorySize,
                             SMEM_TOTAL);
        attr_set = true;
    }
    gemm_kernel<<<dim3(NSZ / BN, MSZ / BM), 512, SMEM_TOTAL>>>(out, scale);    // 3
}